// round 2
// baseline (speedup 1.0000x reference)
#include <cuda_runtime.h>
#include <cuda_bf16.h>
#include <stdint.h>

#define NROWS 4096
#define NCLS  50257
#define EDIM  512
#define BM    128
#define BN    128
#define BK    32
#define LDK   40          // padded bf16 stride: 80B rows -> 16B aligned, conflict-free ldmatrix
#define STAGES 3
#define CTILES ((NCLS + BN - 1) / BN)   // 393
#define KTILES (EDIM / BK)              // 16
#define SMEM_BYTES (STAGES * (BM + BN) * LDK * 2)  // 61440

// ---- scratch (device globals: allocation-free rule) ----
__device__ __nv_bfloat16 g_nx[(size_t)NROWS * EDIM];
__device__ __nv_bfloat16 g_nw[(size_t)NCLS * EDIM];
__device__ float g_invx[NROWS];
__device__ float g_invw[NCLS];
__device__ float g_tcos[NROWS];
__device__ float g_partial[(size_t)CTILES * NROWS];
__device__ float g_rowloss[NROWS];
__device__ int   g_lab64;

// margin = 4.0 rad
#define COSM (-0.6536436208636119f)
#define SINM (-0.7568024953079282f)

// ============================================================
// Row L2-normalize fp32 -> bf16, record 1/max(norm, eps)
// which: 0 -> x (g_nx/g_invx), 1 -> weight (g_nw/g_invw)
// one block (128 thr) per row, 4 floats per thread
// ============================================================
__global__ void normalize_rows(const float* __restrict__ src, int which) {
    int row = blockIdx.x;
    __nv_bfloat16* dst = which ? g_nw : g_nx;
    float* inv         = which ? g_invw : g_invx;

    const float4* s4 = (const float4*)(src + (size_t)row * EDIM);
    float4 a = s4[threadIdx.x];
    float ss = a.x * a.x + a.y * a.y + a.z * a.z + a.w * a.w;
    #pragma unroll
    for (int o = 16; o; o >>= 1) ss += __shfl_xor_sync(0xFFFFFFFFu, ss, o);

    __shared__ float ws[4];
    int wid = threadIdx.x >> 5, lid = threadIdx.x & 31;
    if (lid == 0) ws[wid] = ss;
    __syncthreads();
    float tot = ws[0] + ws[1] + ws[2] + ws[3];
    float invn = 1.0f / fmaxf(sqrtf(tot), 1e-12f);
    if (threadIdx.x == 0) inv[row] = invn;

    __nv_bfloat162 p0 = __floats2bfloat162_rn(a.x * invn, a.y * invn);
    __nv_bfloat162 p1 = __floats2bfloat162_rn(a.z * invn, a.w * invn);
    __nv_bfloat162* d2 = (__nv_bfloat162*)(dst + (size_t)row * EDIM);
    d2[threadIdx.x * 2]     = p0;
    d2[threadIdx.x * 2 + 1] = p1;
}

// ============================================================
// Detect label dtype: int64 labels are all < 2^32 when read as u64.
// int32 data read as u64 pairs has a nonzero high word almost surely.
// ============================================================
__global__ void detect_label(const unsigned long long* __restrict__ lab) {
    __shared__ int bad;
    if (threadIdx.x == 0) bad = 0;
    __syncthreads();
    for (int i = threadIdx.x; i < NROWS / 2; i += blockDim.x)
        if (lab[i] >= (1ull << 32)) bad = 1;   // benign race
    __syncthreads();
    if (threadIdx.x == 0) g_lab64 = bad ? 0 : 1;
}

// ============================================================
// Target cosine in fp32: t[n] = dot(x[n], w[label[n]]) * invx[n] * invw[lab]
// one warp per row
// ============================================================
__global__ void target_cos(const float* __restrict__ x,
                           const void* __restrict__ labp,
                           const float* __restrict__ w) {
    int gw   = blockIdx.x * (blockDim.x >> 5) + (threadIdx.x >> 5);
    int lane = threadIdx.x & 31;
    long long lab;
    if (g_lab64) lab = ((const long long*)labp)[gw];
    else         lab = (long long)(((const int*)labp)[gw]);

    const float4* xa = (const float4*)(x + (size_t)gw * EDIM);
    const float4* wa = (const float4*)(w + (size_t)lab * EDIM);
    float dot = 0.f;
    #pragma unroll
    for (int i = 0; i < 4; i++) {
        float4 a = xa[lane + i * 32];
        float4 b = wa[lane + i * 32];
        dot += a.x * b.x + a.y * b.y + a.z * b.z + a.w * b.w;
    }
    #pragma unroll
    for (int o = 16; o; o >>= 1) dot += __shfl_xor_sync(0xFFFFFFFFu, dot, o);
    if (lane == 0) g_tcos[gw] = dot * g_invx[gw] * g_invw[lab];
}

// ============================================================
// Main fused GEMM + exp-sum epilogue.
// cos_tile = nx[bm:bm+128] @ nw[bc:bc+128]^T via mma.sync bf16.
// partial[ctile][row] = sum over 128 classes of exp(cos) (masked at C).
// ============================================================
__device__ __forceinline__ void cp16(void* s, const void* g) {
    uint32_t sa = (uint32_t)__cvta_generic_to_shared(s);
    asm volatile("cp.async.cg.shared.global [%0], [%1], 16;\n" :: "r"(sa), "l"(g));
}

__device__ __forceinline__ void prefetch_tiles(__nv_bfloat16* As, __nv_bfloat16* Bs,
                                               int tid, int bm, int bc,
                                               int kt, int st) {
    int k0 = kt * BK;
    #pragma unroll
    for (int i = 0; i < 2; i++) {
        int idx = tid + i * 256;
        int row = idx >> 2, ch = idx & 3;
        cp16(As + st * BM * LDK + row * LDK + ch * 8,
             g_nx + (size_t)(bm + row) * EDIM + k0 + ch * 8);
    }
    #pragma unroll
    for (int i = 0; i < 2; i++) {
        int idx = tid + i * 256;
        int row = idx >> 2, ch = idx & 3;
        int c = bc + row;
        if (c >= NCLS) c = NCLS - 1;   // dup row; masked in epilogue
        cp16(Bs + st * BN * LDK + row * LDK + ch * 8,
             g_nw + (size_t)c * EDIM + k0 + ch * 8);
    }
}

extern __shared__ __align__(16) char smem_raw[];

__global__ __launch_bounds__(256, 1) void gemm_expsum() {
    __nv_bfloat16* As = (__nv_bfloat16*)smem_raw;
    __nv_bfloat16* Bs = As + STAGES * BM * LDK;

    const int tid  = threadIdx.x;
    const int lane = tid & 31;
    const int warp = tid >> 5;
    const int wm = warp >> 2;      // 0..1, 64 rows each
    const int wn = warp & 3;       // 0..3, 32 cols each
    const int bm = blockIdx.x * BM;
    const int bc = blockIdx.y * BN;

    float acc[4][4][4] = {};

    prefetch_tiles(As, Bs, tid, bm, bc, 0, 0);
    asm volatile("cp.async.commit_group;\n" ::);
    prefetch_tiles(As, Bs, tid, bm, bc, 1, 1);
    asm volatile("cp.async.commit_group;\n" ::);

    for (int kt = 0; kt < KTILES; kt++) {
        asm volatile("cp.async.wait_group 1;\n" ::);
        __syncthreads();
        if (kt + 2 < KTILES)
            prefetch_tiles(As, Bs, tid, bm, bc, kt + 2, (kt + 2) % STAGES);
        asm volatile("cp.async.commit_group;\n" ::);   // empty groups keep numbering uniform

        const __nv_bfloat16* Ab = As + (kt % STAGES) * BM * LDK;
        const __nv_bfloat16* Bb = Bs + (kt % STAGES) * BN * LDK;

        #pragma unroll
        for (int kk = 0; kk < 2; kk++) {
            uint32_t af[4][4], bf[4][2];
            #pragma unroll
            for (int mi = 0; mi < 4; mi++) {
                int r = wm * 64 + mi * 16 + (lane & 15);
                int c = kk * 16 + (lane >> 4) * 8;
                uint32_t addr = (uint32_t)__cvta_generic_to_shared(Ab + r * LDK + c);
                asm volatile("ldmatrix.sync.aligned.m8n8.x4.shared.b16 {%0,%1,%2,%3}, [%4];\n"
                    : "=r"(af[mi][0]), "=r"(af[mi][1]), "=r"(af[mi][2]), "=r"(af[mi][3])
                    : "r"(addr));
            }
            #pragma unroll
            for (int ni = 0; ni < 4; ni++) {
                int r = wn * 32 + ni * 8 + (lane & 7);
                int c = kk * 16 + ((lane >> 3) & 1) * 8;
                uint32_t addr = (uint32_t)__cvta_generic_to_shared(Bb + r * LDK + c);
                asm volatile("ldmatrix.sync.aligned.m8n8.x2.shared.b16 {%0,%1}, [%2];\n"
                    : "=r"(bf[ni][0]), "=r"(bf[ni][1]) : "r"(addr));
            }
            #pragma unroll
            for (int mi = 0; mi < 4; mi++)
                #pragma unroll
                for (int ni = 0; ni < 4; ni++) {
                    asm volatile(
                        "mma.sync.aligned.m16n8k16.row.col.f32.bf16.bf16.f32 "
                        "{%0,%1,%2,%3}, {%4,%5,%6,%7}, {%8,%9}, {%0,%1,%2,%3};\n"
                        : "+f"(acc[mi][ni][0]), "+f"(acc[mi][ni][1]),
                          "+f"(acc[mi][ni][2]), "+f"(acc[mi][ni][3])
                        : "r"(af[mi][0]), "r"(af[mi][1]), "r"(af[mi][2]), "r"(af[mi][3]),
                          "r"(bf[ni][0]), "r"(bf[ni][1]));
                }
        }
    }
    __syncthreads();   // all smem reads done; reuse smem for row-sum staging

    float* part = (float*)smem_raw;    // [4][BM] indexed [wn][row]
    #pragma unroll
    for (int mi = 0; mi < 4; mi++) {
        float rs0 = 0.f, rs1 = 0.f;
        #pragma unroll
        for (int ni = 0; ni < 4; ni++) {
            int col = bc + wn * 32 + ni * 8 + 2 * (lane & 3);
            float e0 = (col     < NCLS) ? __expf(acc[mi][ni][0]) : 0.f;
            float e1 = (col + 1 < NCLS) ? __expf(acc[mi][ni][1]) : 0.f;
            float e2 = (col     < NCLS) ? __expf(acc[mi][ni][2]) : 0.f;
            float e3 = (col + 1 < NCLS) ? __expf(acc[mi][ni][3]) : 0.f;
            rs0 += e0 + e1;
            rs1 += e2 + e3;
        }
        rs0 += __shfl_xor_sync(0xFFFFFFFFu, rs0, 1);
        rs0 += __shfl_xor_sync(0xFFFFFFFFu, rs0, 2);
        rs1 += __shfl_xor_sync(0xFFFFFFFFu, rs1, 1);
        rs1 += __shfl_xor_sync(0xFFFFFFFFu, rs1, 2);
        if ((lane & 3) == 0) {
            int r = wm * 64 + mi * 16 + (lane >> 2);
            part[wn * BM + r]     = rs0;
            part[wn * BM + r + 8] = rs1;
        }
    }
    __syncthreads();
    if (tid < BM) {
        float s = part[tid] + part[BM + tid] + part[2 * BM + tid] + part[3 * BM + tid];
        g_partial[(size_t)blockIdx.y * NROWS + bm + tid] = s;
    }
}

// ============================================================
// Per-row loss: S = sum of partials; swap target logit for margin logit.
// ============================================================
__global__ void row_loss() {
    int n = blockIdx.x * blockDim.x + threadIdx.x;
    float S = 0.f;
    for (int ct = 0; ct < CTILES; ct++)
        S += g_partial[(size_t)ct * NROWS + n];
    float t  = g_tcos[n];
    float st = sqrtf(fmaxf(1.f - t * t, 0.f));
    float cm = t * COSM - st * SINM;
    float Sp = S - __expf(t) + __expf(cm);
    g_rowloss[n] = logf(Sp) - cm;
}

// ============================================================
// Mean over rows (deterministic tree)
// ============================================================
__global__ void reduce_loss(float* __restrict__ out) {
    __shared__ float red[1024];
    int tid = threadIdx.x;
    float s = g_rowloss[tid] + g_rowloss[tid + 1024] +
              g_rowloss[tid + 2048] + g_rowloss[tid + 3072];
    red[tid] = s;
    __syncthreads();
    for (int o = 512; o; o >>= 1) {
        if (tid < o) red[tid] += red[tid + o];
        __syncthreads();
    }
    if (tid == 0) out[0] = red[0] * (1.0f / NROWS);
}

// ============================================================
extern "C" void kernel_launch(void* const* d_in, const int* in_sizes, int n_in,
                              void* d_out, int out_size) {
    const float* x   = (const float*)d_in[0];
    const void*  lab = d_in[1];
    const float* w   = (const float*)d_in[2];
    float* out = (float*)d_out;

    cudaFuncSetAttribute(gemm_expsum, cudaFuncAttributeMaxDynamicSharedMemorySize, SMEM_BYTES);

    normalize_rows<<<NROWS, 128>>>(x, 0);
    normalize_rows<<<NCLS, 128>>>(w, 1);
    detect_label<<<1, 256>>>((const unsigned long long*)lab);
    target_cos<<<NROWS / 32, 1024>>>(x, lab, w);
    gemm_expsum<<<dim3(NROWS / BM, CTILES), 256, SMEM_BYTES>>>();
    row_loss<<<NROWS / 256, 256>>>();
    reduce_loss<<<1, 1024>>>(out);
}

// round 5
// speedup vs baseline: 1.6834x; 1.6834x over previous
#include <cuda_runtime.h>
#include <cuda_bf16.h>
#include <stdint.h>

#define NROWS 4096
#define NCLS  50257
#define EDIM  512
#define BM    128
#define BN    128
#define BK    64           // 64 bf16 = 128B row = SW128 atom
#define NSTG  3
#define NT    ((NCLS + BN - 1) / BN)   // 393
#define KCHUNKS (EDIM / BK)            // 8

#define A_BYTES   (BM * 128)           // 16384
#define B_BYTES   (BN * 128)           // 16384
#define STG_BYTES (A_BYTES + B_BYTES)  // 32768
#define SMEM_TOTAL (NSTG * STG_BYTES)  // 98304

// ---- scratch (device globals: allocation-free rule) ----
__device__ __nv_bfloat16 g_nx[(size_t)NROWS * EDIM];
__device__ __nv_bfloat16 g_nw[(size_t)NCLS * EDIM];
__device__ float g_invx[NROWS];
__device__ float g_invw[NCLS];
__device__ float g_tcos[NROWS];
__device__ float g_partial[(size_t)NT * NROWS];
__device__ float g_rowloss[NROWS];
__device__ int   g_lab64;

// margin = 4.0 rad
#define COSM (-0.6536436208636119f)
#define SINM (-0.7568024953079282f)

// ============================================================ helpers
__device__ __forceinline__ uint32_t s2u(const void* p) {
    uint32_t a;
    asm("{ .reg .u64 t; cvta.to.shared.u64 t, %1; cvt.u32.u64 %0, t; }" : "=r"(a) : "l"(p));
    return a;
}
__device__ __forceinline__ void cp16(uint32_t saddr, const void* g) {
    asm volatile("cp.async.cg.shared.global [%0], [%1], 16;\n" :: "r"(saddr), "l"(g));
}
__device__ __forceinline__ uint32_t sw128(uint32_t off) {
    return off ^ ((off >> 3) & 0x70);
}

// ============================================================
// Row L2-normalize fp32 -> bf16
// ============================================================
__global__ void normalize_rows(const float* __restrict__ src, int which) {
    int row = blockIdx.x;
    __nv_bfloat16* dst = which ? g_nw : g_nx;
    float* inv         = which ? g_invw : g_invx;

    const float4* s4 = (const float4*)(src + (size_t)row * EDIM);
    float4 a = s4[threadIdx.x];
    float ss = a.x * a.x + a.y * a.y + a.z * a.z + a.w * a.w;
    #pragma unroll
    for (int o = 16; o; o >>= 1) ss += __shfl_xor_sync(0xFFFFFFFFu, ss, o);

    __shared__ float ws[4];
    int wid = threadIdx.x >> 5, lid = threadIdx.x & 31;
    if (lid == 0) ws[wid] = ss;
    __syncthreads();
    float tot = ws[0] + ws[1] + ws[2] + ws[3];
    float invn = 1.0f / fmaxf(sqrtf(tot), 1e-12f);
    if (threadIdx.x == 0) inv[row] = invn;

    __nv_bfloat162 p0 = __floats2bfloat162_rn(a.x * invn, a.y * invn);
    __nv_bfloat162 p1 = __floats2bfloat162_rn(a.z * invn, a.w * invn);
    __nv_bfloat162* d2 = (__nv_bfloat162*)(dst + (size_t)row * EDIM);
    d2[threadIdx.x * 2]     = p0;
    d2[threadIdx.x * 2 + 1] = p1;
}

// ============================================================
__global__ void detect_label(const unsigned long long* __restrict__ lab) {
    __shared__ int bad;
    if (threadIdx.x == 0) bad = 0;
    __syncthreads();
    for (int i = threadIdx.x; i < NROWS / 2; i += blockDim.x)
        if (lab[i] >= (1ull << 32)) bad = 1;
    __syncthreads();
    if (threadIdx.x == 0) g_lab64 = bad ? 0 : 1;
}

// ============================================================
__global__ void target_cos(const float* __restrict__ x,
                           const void* __restrict__ labp,
                           const float* __restrict__ w) {
    int gw   = blockIdx.x * (blockDim.x >> 5) + (threadIdx.x >> 5);
    int lane = threadIdx.x & 31;
    long long lab;
    if (g_lab64) lab = ((const long long*)labp)[gw];
    else         lab = (long long)(((const int*)labp)[gw]);

    const float4* xa = (const float4*)(x + (size_t)gw * EDIM);
    const float4* wa = (const float4*)(w + (size_t)lab * EDIM);
    float dot = 0.f;
    #pragma unroll
    for (int i = 0; i < 4; i++) {
        float4 a = xa[lane + i * 32];
        float4 b = wa[lane + i * 32];
        dot += a.x * b.x + a.y * b.y + a.z * b.z + a.w * b.w;
    }
    #pragma unroll
    for (int o = 16; o; o >>= 1) dot += __shfl_xor_sync(0xFFFFFFFFu, dot, o);
    if (lane == 0) g_tcos[gw] = dot * g_invx[gw] * g_invw[lab];
}

// ============================================================
// mma.sync bf16 GEMM + fused exp-sum epilogue, occupancy 2.
// SW128-swizzled smem tiles (128B rows), 3-stage cp.async, BK=64.
// ============================================================
__device__ __forceinline__ void prefetch_chunk(uint32_t sbase, int tid,
                                               int bm, int bc, int kt, int st) {
    int k0 = kt * BK;
    uint32_t abase = sbase + st * STG_BYTES;
    // A: 128 rows x 8 segs of 16B = 1024 segs
    #pragma unroll
    for (int i = 0; i < 4; i++) {
        int idx = tid + i * 256;
        int r = idx >> 3, s = idx & 7;
        cp16(abase + sw128((uint32_t)(r * 128 + s * 16)),
             g_nx + (size_t)(bm + r) * EDIM + k0 + s * 8);
    }
    // B: 128 class rows (clamped; masked in epilogue)
    #pragma unroll
    for (int i = 0; i < 4; i++) {
        int idx = tid + i * 256;
        int r = idx >> 3, s = idx & 7;
        int c = bc + r;
        if (c >= NCLS) c = NCLS - 1;
        cp16(abase + A_BYTES + sw128((uint32_t)(r * 128 + s * 16)),
             g_nw + (size_t)c * EDIM + k0 + s * 8);
    }
}

extern __shared__ __align__(16) char smem_raw[];

__global__ __launch_bounds__(256, 2) void gemm_expsum() {
    uint32_t sbase = s2u(smem_raw);
    const int tid  = threadIdx.x;
    const int lane = tid & 31;
    const int warp = tid >> 5;
    const int wm = warp >> 2;      // 0..1, 64 rows each
    const int wn = warp & 3;       // 0..3, 32 cols each
    const int bm = blockIdx.x * BM;
    const int bc = blockIdx.y * BN;

    float acc[4][4][4] = {};

    prefetch_chunk(sbase, tid, bm, bc, 0, 0);
    asm volatile("cp.async.commit_group;\n" ::);
    prefetch_chunk(sbase, tid, bm, bc, 1, 1);
    asm volatile("cp.async.commit_group;\n" ::);

    // Per-thread ldmatrix byte offsets (within tile, before swizzle)
    const uint32_t a_row = (uint32_t)(wm * 64 + (lane & 15));
    const uint32_t a_seg = (uint32_t)(lane >> 4);          // 0..1
    const uint32_t b_row = (uint32_t)(wn * 32 + (lane & 7));
    const uint32_t b_seg = (uint32_t)((lane >> 3) & 1);    // 0..1

    for (int kt = 0; kt < KCHUNKS; kt++) {
        asm volatile("cp.async.wait_group 1;\n" ::);
        __syncthreads();
        if (kt + 2 < KCHUNKS)
            prefetch_chunk(sbase, tid, bm, bc, kt + 2, (kt + 2) % NSTG);
        asm volatile("cp.async.commit_group;\n" ::);

        uint32_t Ab = sbase + (kt % NSTG) * STG_BYTES;
        uint32_t Bb = Ab + A_BYTES;

        #pragma unroll
        for (int kk = 0; kk < 4; kk++) {
            uint32_t af[4][4], bf[4][2];
            #pragma unroll
            for (int mi = 0; mi < 4; mi++) {
                uint32_t off = (a_row + mi * 16) * 128 + kk * 32 + a_seg * 16;
                uint32_t addr = Ab + sw128(off);
                asm volatile("ldmatrix.sync.aligned.m8n8.x4.shared.b16 {%0,%1,%2,%3}, [%4];\n"
                    : "=r"(af[mi][0]), "=r"(af[mi][1]), "=r"(af[mi][2]), "=r"(af[mi][3])
                    : "r"(addr));
            }
            #pragma unroll
            for (int ni = 0; ni < 4; ni++) {
                uint32_t off = (b_row + ni * 8) * 128 + kk * 32 + b_seg * 16;
                uint32_t addr = Bb + sw128(off);
                asm volatile("ldmatrix.sync.aligned.m8n8.x2.shared.b16 {%0,%1}, [%2];\n"
                    : "=r"(bf[ni][0]), "=r"(bf[ni][1]) : "r"(addr));
            }
            #pragma unroll
            for (int mi = 0; mi < 4; mi++)
                #pragma unroll
                for (int ni = 0; ni < 4; ni++) {
                    asm volatile(
                        "mma.sync.aligned.m16n8k16.row.col.f32.bf16.bf16.f32 "
                        "{%0,%1,%2,%3}, {%4,%5,%6,%7}, {%8,%9}, {%0,%1,%2,%3};\n"
                        : "+f"(acc[mi][ni][0]), "+f"(acc[mi][ni][1]),
                          "+f"(acc[mi][ni][2]), "+f"(acc[mi][ni][3])
                        : "r"(af[mi][0]), "r"(af[mi][1]), "r"(af[mi][2]), "r"(af[mi][3]),
                          "r"(bf[ni][0]), "r"(bf[ni][1]));
                }
        }
    }
    __syncthreads();   // all smem reads done; reuse smem for row-sum staging

    float* part = (float*)smem_raw;    // [4][BM] indexed [wn][row]
    #pragma unroll
    for (int mi = 0; mi < 4; mi++) {
        float rs0 = 0.f, rs1 = 0.f;
        #pragma unroll
        for (int ni = 0; ni < 4; ni++) {
            int col = bc + wn * 32 + ni * 8 + 2 * (lane & 3);
            float e0 = (col     < NCLS) ? __expf(acc[mi][ni][0]) : 0.f;
            float e1 = (col + 1 < NCLS) ? __expf(acc[mi][ni][1]) : 0.f;
            float e2 = (col     < NCLS) ? __expf(acc[mi][ni][2]) : 0.f;
            float e3 = (col + 1 < NCLS) ? __expf(acc[mi][ni][3]) : 0.f;
            rs0 += e0 + e1;
            rs1 += e2 + e3;
        }
        rs0 += __shfl_xor_sync(0xFFFFFFFFu, rs0, 1);
        rs0 += __shfl_xor_sync(0xFFFFFFFFu, rs0, 2);
        rs1 += __shfl_xor_sync(0xFFFFFFFFu, rs1, 1);
        rs1 += __shfl_xor_sync(0xFFFFFFFFu, rs1, 2);
        if ((lane & 3) == 0) {
            int r = wm * 64 + mi * 16 + (lane >> 2);
            part[wn * BM + r]     = rs0;
            part[wn * BM + r + 8] = rs1;
        }
    }
    __syncthreads();
    if (tid < BM) {
        float s = part[tid] + part[BM + tid] + part[2 * BM + tid] + part[3 * BM + tid];
        g_partial[(size_t)blockIdx.y * NROWS + bm + tid] = s;
    }
}

// ============================================================
__global__ void row_loss() {
    int n = blockIdx.x * blockDim.x + threadIdx.x;
    float S = 0.f;
    for (int ct = 0; ct < NT; ct++)
        S += g_partial[(size_t)ct * NROWS + n];
    float t  = g_tcos[n];
    float st = sqrtf(fmaxf(1.f - t * t, 0.f));
    float cm = t * COSM - st * SINM;
    float Sp = S - __expf(t) + __expf(cm);
    g_rowloss[n] = logf(Sp) - cm;
}

// ============================================================
__global__ void reduce_loss(float* __restrict__ out) {
    __shared__ float red[1024];
    int tid = threadIdx.x;
    float s = g_rowloss[tid] + g_rowloss[tid + 1024] +
              g_rowloss[tid + 2048] + g_rowloss[tid + 3072];
    red[tid] = s;
    __syncthreads();
    for (int o = 512; o; o >>= 1) {
        if (tid < o) red[tid] += red[tid + o];
        __syncthreads();
    }
    if (tid == 0) out[0] = red[0] * (1.0f / NROWS);
}

// ============================================================
extern "C" void kernel_launch(void* const* d_in, const int* in_sizes, int n_in,
                              void* d_out, int out_size) {
    const float* x   = (const float*)d_in[0];
    const void*  lab = d_in[1];
    const float* w   = (const float*)d_in[2];
    float* out = (float*)d_out;

    cudaFuncSetAttribute(gemm_expsum, cudaFuncAttributeMaxDynamicSharedMemorySize, SMEM_TOTAL);

    normalize_rows<<<NROWS, 128>>>(x, 0);
    normalize_rows<<<NCLS, 128>>>(w, 1);
    detect_label<<<1, 256>>>((const unsigned long long*)lab);
    target_cos<<<NROWS / 32, 1024>>>(x, lab, w);
    gemm_expsum<<<dim3(NROWS / BM, NT), 256, SMEM_TOTAL>>>();
    row_loss<<<NROWS / 256, 256>>>();
    reduce_loss<<<1, 1024>>>(out);
}